// round 5
// baseline (speedup 1.0000x reference)
#include <cuda_runtime.h>

#define TFULL 2048
#define CIN   64
#define DMODEL 128
#define SNUM  3
#define BNUM  2
#define HNUM  8
#define DH    16
#define KHALF 1024

typedef unsigned long long u64;

__device__ __forceinline__ u64 pack2(float lo, float hi) {
    u64 r; asm("mov.b64 %0,{%1,%2};" : "=l"(r) : "f"(lo), "f"(hi)); return r;
}
__device__ __forceinline__ void unpack2(u64 v, float& lo, float& hi) {
    asm("mov.b64 {%0,%1},%2;" : "=f"(lo), "=f"(hi) : "l"(v));
}
__device__ __forceinline__ u64 ffma2(u64 a, u64 b, u64 c) {
    u64 d; asm("fma.rn.f32x2 %0,%1,%2,%3;" : "=l"(d) : "l"(a), "l"(b), "l"(c)); return d;
}
__device__ __forceinline__ u64 fmul2(u64 a, u64 b) {
    u64 d; asm("mul.rn.f32x2 %0,%1,%2;" : "=l"(d) : "l"(a), "l"(b)); return d;
}
__device__ __forceinline__ u64 fadd2(u64 a, u64 b) {
    u64 d; asm("add.rn.f32x2 %0,%1,%2;" : "=l"(d) : "l"(a), "l"(b)); return d;
}

// ---------------- wavelet filters ----------------
__constant__ float c_DEC_LO[8] = {
    -0.010597401784997278f,  0.032883011666982945f,  0.030841381835986965f,
    -0.18703481171888114f,  -0.02798376941698385f,   0.6308807679295904f,
     0.7148465705525415f,    0.23037781330885523f };
__constant__ float c_DEC_HI[8] = {
    -0.23037781330885523f,   0.7148465705525415f,   -0.6308807679295904f,
    -0.02798376941698385f,   0.18703481171888114f,   0.030841381835986965f,
    -0.032883011666982945f, -0.010597401784997278f };

// ---------------- scratch ----------------
__device__ float g_W   [SNUM*BNUM*TFULL*CIN];
__device__ float g_A   [SNUM*3*DMODEL*CIN];
__device__ float g_cb  [SNUM*3*DMODEL];
__device__ float g_q   [SNUM*BNUM*TFULL*DMODEL];
__device__ float g_k   [SNUM*BNUM*TFULL*DMODEL];
__device__ float g_v   [SNUM*BNUM*TFULL*DMODEL];
__device__ float g_o   [SNUM*BNUM*TFULL*DMODEL];
__device__ float g_pacc[2*SNUM*BNUM*TFULL*HNUM*DH];   // split-K partial acc
__device__ float g_pml [2*SNUM*BNUM*TFULL*HNUM*2];    // split-K partial (m,l)
__device__ float g_meanp[SNUM*BNUM*16*DMODEL];
__device__ float g_gate[BNUM*SNUM];

// ================= K0: stationary wavelet transform =================
__global__ void k_swt(const float* __restrict__ x) {
    __shared__ float sh[2][TFULL];
    const int b = blockIdx.x >> 6;
    const int c = blockIdx.x & 63;
    const int tid = threadIdx.x;

    for (int t = tid; t < TFULL; t += 256)
        sh[0][t] = x[(b * TFULL + t) * CIN + c];
    __syncthreads();

    int cur = 0;
    for (int j = 0; j < 3; j++) {
        const int step = 1 << j;
        for (int t = tid; t < TFULL; t += 256) {
            float d = 0.f, a = 0.f;
#pragma unroll
            for (int l = 0; l < 8; l++) {
                float val = sh[cur][(t - l * step) & (TFULL - 1)];
                d += val * c_DEC_HI[l];
                a += val * c_DEC_LO[l];
            }
            g_W[(((2 - j) * BNUM + b) * TFULL + t) * CIN + c] = d;
            sh[cur ^ 1][t] = a;
        }
        __syncthreads();
        cur ^= 1;
    }
}

// ================= K1: compose (in_w x Wqkv) weights + biases =================
__global__ void k_compose(const float* __restrict__ Wq, const float* __restrict__ bq,
                          const float* __restrict__ Wk, const float* __restrict__ bk,
                          const float* __restrict__ Wv, const float* __restrict__ bv,
                          const float* __restrict__ in_w, const float* __restrict__ in_b) {
    const int sw = blockIdx.x;
    const int s = sw / 3, w = sw % 3;
    const float* Wx = (w == 0) ? Wq : (w == 1) ? Wk : Wv;
    const float* bx = (w == 0) ? bq : (w == 1) ? bk : bv;

    const int idx = blockIdx.y * 256 + threadIdx.x;
    const int e = idx >> 6, c = idx & 63;
    const float* iw = in_w + (w * DMODEL + e) * DMODEL;
    const float* wc = Wx + s * DMODEL * CIN + c;
    float acc = 0.f;
#pragma unroll 4
    for (int dd = 0; dd < DMODEL; dd++) acc += iw[dd] * wc[dd * CIN];
    g_A[(sw * DMODEL + e) * CIN + c] = acc;

    if (blockIdx.y == 0 && threadIdx.x < DMODEL) {
        const int ee = threadIdx.x;
        const float* iw2 = in_w + (w * DMODEL + ee) * DMODEL;
        float bb = in_b[w * DMODEL + ee];
#pragma unroll 4
        for (int dd = 0; dd < DMODEL; dd++) bb += iw2[dd] * bx[s * DMODEL + dd];
        g_cb[sw * DMODEL + ee] = bb;
    }
}

// ================= K2: fused q/k/v projection GEMM =================
__global__ void __launch_bounds__(256) k_qkv() {
    __shared__ float shW[64][33];
    __shared__ float shA[128][33];
    const int row0 = blockIdx.x * 64;
    const int w = blockIdx.y;
    const int s = row0 >> 12;
    const int tid = threadIdx.x;
    const int ty = tid >> 4, tx = tid & 15;
    const float* Abase = g_A + (s * 3 + w) * DMODEL * CIN;

    float acc[4][8];
#pragma unroll
    for (int i = 0; i < 4; i++)
#pragma unroll
        for (int j = 0; j < 8; j++) acc[i][j] = 0.f;

    for (int c0 = 0; c0 < CIN; c0 += 32) {
#pragma unroll
        for (int i = 0; i < 8; i++) {
            int lin = tid + i * 256;
            shW[lin >> 5][lin & 31] = g_W[(row0 + (lin >> 5)) * CIN + c0 + (lin & 31)];
        }
#pragma unroll
        for (int i = 0; i < 16; i++) {
            int lin = tid + i * 256;
            shA[lin >> 5][lin & 31] = Abase[(lin >> 5) * CIN + c0 + (lin & 31)];
        }
        __syncthreads();
#pragma unroll
        for (int cc = 0; cc < 32; cc++) {
            float wr[4], ar[8];
#pragma unroll
            for (int i = 0; i < 4; i++) wr[i] = shW[i * 16 + ty][cc];
#pragma unroll
            for (int j = 0; j < 8; j++) ar[j] = shA[j * 16 + tx][cc];
#pragma unroll
            for (int i = 0; i < 4; i++)
#pragma unroll
                for (int j = 0; j < 8; j++) acc[i][j] += wr[i] * ar[j];
        }
        __syncthreads();
    }

    float* out = (w == 0) ? g_q : (w == 1) ? g_k : g_v;
    const float* cb = g_cb + (s * 3 + w) * DMODEL;
#pragma unroll
    for (int i = 0; i < 4; i++) {
        int r = row0 + i * 16 + ty;
#pragma unroll
        for (int j = 0; j < 8; j++) {
            int e = j * 16 + tx;
            out[r * DMODEL + e] = acc[i][j] + cb[e];
        }
    }
}

// ================= K3: flash attention, split-K, 64-thread blocks, 2q/thread =================
// grid: (16 q-tiles of 128, 8 heads, 6 s*b * 2 key-halves). block 64. No reg cap.
__global__ void k_attn() {
    __shared__ float4 shK4[128][4];
    __shared__ float4 shV4[128][4];
    const int tid = threadIdx.x;
    const int qt = blockIdx.x, h = blockIdx.y;
    const int sb = blockIdx.z >> 1, kh = blockIdx.z & 1;

    const float* qb = g_q + (size_t)sb * TFULL * DMODEL + h * DH;
    const float* kb = g_k + (size_t)sb * TFULL * DMODEL + h * DH;
    const float* vb = g_v + (size_t)sb * TFULL * DMODEL + h * DH;

    const float sc = 0.25f * 1.4426950408889634f;   // 1/sqrt(16) * log2(e)
    const int t0 = qt * 128 + tid;
    const int t1 = t0 + 64;

    u64 qp[2][8];
#pragma unroll
    for (int qi = 0; qi < 2; qi++) {
        const float* qr = qb + (size_t)(qi ? t1 : t0) * DMODEL;
#pragma unroll
        for (int i = 0; i < 4; i++) {
            float4 a = *(const float4*)(qr + i * 4);
            qp[qi][i * 2 + 0] = pack2(a.x * sc, a.y * sc);
            qp[qi][i * 2 + 1] = pack2(a.z * sc, a.w * sc);
        }
    }

    float m0 = -1e30f, m1 = -1e30f, l0 = 0.f, l1 = 0.f;
    u64 acc0[8], acc1[8];
    const u64 zz = pack2(0.f, 0.f);
#pragma unroll
    for (int i = 0; i < 8; i++) { acc0[i] = zz; acc1[i] = zz; }

    const int kbeg = kh * KHALF;
    for (int kc = kbeg; kc < kbeg + KHALF; kc += 128) {
#pragma unroll
        for (int i = 0; i < 8; i++) {
            int lin = tid + i * 64;                 // 512 float4 each buffer
            int r = lin >> 2, c = lin & 3;
            shK4[r][c] = *(const float4*)(kb + (size_t)(kc + r) * DMODEL + c * 4);
            shV4[r][c] = *(const float4*)(vb + (size_t)(kc + r) * DMODEL + c * 4);
        }
        __syncthreads();

#pragma unroll 1
        for (int j0 = 0; j0 < 128; j0 += 8) {
            float s0[8], s1[8];
#pragma unroll
            for (int jj = 0; jj < 8; jj++) {
                const ulonglong2* kr = (const ulonglong2*)&shK4[j0 + jj][0];
                ulonglong2 ka = kr[0], kb2 = kr[1];
                // query 0: even/odd dual chains (depth 4 each)
                u64 e0 = fmul2(qp[0][0], ka.x);
                u64 o0 = fmul2(qp[0][1], ka.y);
                e0 = ffma2(qp[0][2], kb2.x, e0);
                o0 = ffma2(qp[0][3], kb2.y, o0);
                u64 e1 = fmul2(qp[1][0], ka.x);
                u64 o1 = fmul2(qp[1][1], ka.y);
                e1 = ffma2(qp[1][2], kb2.x, e1);
                o1 = ffma2(qp[1][3], kb2.y, o1);
                ulonglong2 kc2 = kr[2], kd = kr[3];
                e0 = ffma2(qp[0][4], kc2.x, e0);
                o0 = ffma2(qp[0][5], kc2.y, o0);
                e0 = ffma2(qp[0][6], kd.x, e0);
                o0 = ffma2(qp[0][7], kd.y, o0);
                e1 = ffma2(qp[1][4], kc2.x, e1);
                o1 = ffma2(qp[1][5], kc2.y, o1);
                e1 = ffma2(qp[1][6], kd.x, e1);
                o1 = ffma2(qp[1][7], kd.y, o1);
                u64 t0s = fadd2(e0, o0);
                u64 t1s = fadd2(e1, o1);
                float lo, hi;
                unpack2(t0s, lo, hi); s0[jj] = lo + hi;
                unpack2(t1s, lo, hi); s1[jj] = lo + hi;
            }
            float mx0 = m0, mx1 = m1;
#pragma unroll
            for (int jj = 0; jj < 8; jj++) { mx0 = fmaxf(mx0, s0[jj]); mx1 = fmaxf(mx1, s1[jj]); }
            float c0 = exp2f(m0 - mx0), c1 = exp2f(m1 - mx1);
            m0 = mx0; m1 = mx1;
            l0 *= c0; l1 *= c1;
            u64 cp0 = pack2(c0, c0), cp1 = pack2(c1, c1);
#pragma unroll
            for (int i = 0; i < 8; i++) { acc0[i] = fmul2(acc0[i], cp0); acc1[i] = fmul2(acc1[i], cp1); }
#pragma unroll
            for (int jj = 0; jj < 8; jj++) {
                float p0 = exp2f(s0[jj] - m0);
                float p1 = exp2f(s1[jj] - m1);
                l0 += p0; l1 += p1;
                s0[jj] = p0; s1[jj] = p1;
            }
#pragma unroll
            for (int jj = 0; jj < 8; jj++) {
                const ulonglong2* vr = (const ulonglong2*)&shV4[j0 + jj][0];
                ulonglong2 va = vr[0], vb2 = vr[1], vc = vr[2], vd = vr[3];
                u64 pp0 = pack2(s0[jj], s0[jj]);
                u64 pp1 = pack2(s1[jj], s1[jj]);
                acc0[0] = ffma2(pp0, va.x, acc0[0]);
                acc0[1] = ffma2(pp0, va.y, acc0[1]);
                acc0[2] = ffma2(pp0, vb2.x, acc0[2]);
                acc0[3] = ffma2(pp0, vb2.y, acc0[3]);
                acc0[4] = ffma2(pp0, vc.x, acc0[4]);
                acc0[5] = ffma2(pp0, vc.y, acc0[5]);
                acc0[6] = ffma2(pp0, vd.x, acc0[6]);
                acc0[7] = ffma2(pp0, vd.y, acc0[7]);
                acc1[0] = ffma2(pp1, va.x, acc1[0]);
                acc1[1] = ffma2(pp1, va.y, acc1[1]);
                acc1[2] = ffma2(pp1, vb2.x, acc1[2]);
                acc1[3] = ffma2(pp1, vb2.y, acc1[3]);
                acc1[4] = ffma2(pp1, vc.x, acc1[4]);
                acc1[5] = ffma2(pp1, vc.y, acc1[5]);
                acc1[6] = ffma2(pp1, vd.x, acc1[6]);
                acc1[7] = ffma2(pp1, vd.y, acc1[7]);
            }
        }
        __syncthreads();
    }

    // write split-K partials
#pragma unroll
    for (int qi = 0; qi < 2; qi++) {
        const u64* ac = qi ? acc1 : acc0;
        const int t = qi ? t1 : t0;
        const size_t base = (((size_t)kh * (SNUM * BNUM) + sb) * TFULL + t) * HNUM + h;
        float* pa = g_pacc + base * DH;
#pragma unroll
        for (int i = 0; i < 4; i++) {
            float x0, y0, x1, y1;
            unpack2(ac[i * 2 + 0], x0, y0);
            unpack2(ac[i * 2 + 1], x1, y1);
            *(float4*)(pa + i * 4) = make_float4(x0, y0, x1, y1);
        }
        float2* pm = (float2*)(g_pml) + base;
        *pm = make_float2(qi ? m1 : m0, qi ? l1 : l0);
    }
}

// ================= K3b: merge split-K partials =================
__global__ void k_merge() {
    const int idx = blockIdx.x * 256 + threadIdx.x;
    const int h = idx & 7;
    const int t = (idx >> 3) & (TFULL - 1);
    const int sb = idx >> 14;
    const size_t base0 = (((size_t)0 * (SNUM * BNUM) + sb) * TFULL + t) * HNUM + h;
    const size_t base1 = (((size_t)1 * (SNUM * BNUM) + sb) * TFULL + t) * HNUM + h;

    float2 ml0 = ((const float2*)g_pml)[base0];
    float2 ml1 = ((const float2*)g_pml)[base1];
    float M = fmaxf(ml0.x, ml1.x);
    float e0 = exp2f(ml0.x - M);
    float e1 = exp2f(ml1.x - M);
    float inv = 1.f / (e0 * ml0.y + e1 * ml1.y);
    e0 *= inv; e1 *= inv;

    const float* pa0 = g_pacc + base0 * DH;
    const float* pa1 = g_pacc + base1 * DH;
    float* ob = g_o + ((size_t)sb * TFULL + t) * DMODEL + h * DH;
#pragma unroll
    for (int i = 0; i < 4; i++) {
        float4 a = *(const float4*)(pa0 + i * 4);
        float4 b = *(const float4*)(pa1 + i * 4);
        *(float4*)(ob + i * 4) = make_float4(a.x * e0 + b.x * e1,
                                             a.y * e0 + b.y * e1,
                                             a.z * e0 + b.z * e1,
                                             a.w * e0 + b.w * e1);
    }
}

// ================= K4: partial t-sums =================
__global__ void k_meanred() {
    const int s = blockIdx.x, b = blockIdx.y, ch = blockIdx.z;
    const int d = threadIdx.x;
    const float* base = g_o + (((size_t)(s * BNUM + b) * TFULL) + ch * 128) * DMODEL + d;
    float sum = 0.f;
#pragma unroll 8
    for (int t = 0; t < 128; t++) sum += base[t * DMODEL];
    g_meanp[((s * BNUM + b) * 16 + ch) * DMODEL + d] = sum;
}

// ================= K5: gate computation =================
__global__ void k_gate(const float* __restrict__ out_w, const float* __restrict__ out_b,
                       const float* __restrict__ gate_w, const float* __restrict__ gate_b) {
    __shared__ float sh_m[DMODEL];
    __shared__ float sh_gf[DMODEL];
    __shared__ float sh_lg[SNUM];
    const int d = threadIdx.x;
    for (int b = 0; b < BNUM; b++) {
        float mv = 0.f;
#pragma unroll
        for (int s = 0; s < SNUM; s++)
#pragma unroll
            for (int c = 0; c < 16; c++)
                mv += g_meanp[((s * BNUM + b) * 16 + c) * DMODEL + d];
        sh_m[d] = mv;
        __syncthreads();
        float acc = 0.f;
        const float* ow = out_w + d * DMODEL;
#pragma unroll 4
        for (int dd = 0; dd < DMODEL; dd++) acc += ow[dd] * sh_m[dd];
        sh_gf[d] = acc * (1.0f / (TFULL * SNUM)) + out_b[d];
        __syncthreads();
        if (d < SNUM) {
            float lg = gate_b[d];
            for (int dd = 0; dd < DMODEL; dd++) lg += sh_gf[dd] * gate_w[d * DMODEL + dd];
            sh_lg[d] = lg;
        }
        __syncthreads();
        if (d == 0) {
            float mx = fmaxf(sh_lg[0], fmaxf(sh_lg[1], sh_lg[2]));
            float e0 = __expf(sh_lg[0] - mx);
            float e1 = __expf(sh_lg[1] - mx);
            float e2 = __expf(sh_lg[2] - mx);
            float inv = 1.f / (e0 + e1 + e2);
            g_gate[b * 3 + 0] = e0 * inv;
            g_gate[b * 3 + 1] = e1 * inv;
            g_gate[b * 3 + 2] = e2 * inv;
        }
        __syncthreads();
    }
}

// ================= K6: gated combine + output projection =================
__global__ void __launch_bounds__(256) k_final(const float* __restrict__ out_w,
                                               const float* __restrict__ out_b,
                                               float* __restrict__ Z) {
    __shared__ float shI[64][33];
    __shared__ float shWt[128][33];
    const int row0 = blockIdx.x * 64;
    const int tid = threadIdx.x;
    const int b = row0 >> 11;
    const float gt0 = g_gate[b * 3 + 0];
    const float gt1 = g_gate[b * 3 + 1];
    const float gt2 = g_gate[b * 3 + 2];
    const int ty = tid >> 4, tx = tid & 15;
    const size_t SB = (size_t)BNUM * TFULL * DMODEL;

    float acc[4][8];
#pragma unroll
    for (int i = 0; i < 4; i++)
#pragma unroll
        for (int j = 0; j < 8; j++) acc[i][j] = 0.f;

    for (int c0 = 0; c0 < DMODEL; c0 += 32) {
#pragma unroll
        for (int i = 0; i < 8; i++) {
            int lin = tid + i * 256;
            int rr = lin >> 5, cc = lin & 31;
            size_t idx = (size_t)(row0 + rr) * DMODEL + c0 + cc;
            float v0 = g_o[idx];
            float v1 = g_o[SB + idx];
            float v2 = g_o[2 * SB + idx];
            shI[rr][cc] = gt0 * v0 + gt1 * v1 + gt2 * v2;
        }
#pragma unroll
        for (int i = 0; i < 16; i++) {
            int lin = tid + i * 256;
            shWt[lin >> 5][lin & 31] = out_w[(lin >> 5) * DMODEL + c0 + (lin & 31)];
        }
        __syncthreads();
#pragma unroll
        for (int cc = 0; cc < 32; cc++) {
            float ir[4], wr[8];
#pragma unroll
            for (int i = 0; i < 4; i++) ir[i] = shI[i * 16 + ty][cc];
#pragma unroll
            for (int j = 0; j < 8; j++) wr[j] = shWt[j * 16 + tx][cc];
#pragma unroll
            for (int i = 0; i < 4; i++)
#pragma unroll
                for (int j = 0; j < 8; j++) acc[i][j] += ir[i] * wr[j];
        }
        __syncthreads();
    }

#pragma unroll
    for (int i = 0; i < 4; i++) {
        int r = row0 + i * 16 + ty;
#pragma unroll
        for (int j = 0; j < 8; j++) {
            int e = j * 16 + tx;
            Z[(size_t)r * DMODEL + e] = acc[i][j] + out_b[e];
        }
    }
}

// ================= launch =================
extern "C" void kernel_launch(void* const* d_in, const int* in_sizes, int n_in,
                              void* d_out, int out_size) {
    const float* x      = (const float*)d_in[0];
    const float* Wq     = (const float*)d_in[1];
    const float* bq     = (const float*)d_in[2];
    const float* Wk     = (const float*)d_in[3];
    const float* bk     = (const float*)d_in[4];
    const float* Wv     = (const float*)d_in[5];
    const float* bv     = (const float*)d_in[6];
    const float* in_w   = (const float*)d_in[7];
    const float* in_b   = (const float*)d_in[8];
    const float* out_w  = (const float*)d_in[9];
    const float* out_b  = (const float*)d_in[10];
    const float* gate_w = (const float*)d_in[11];
    const float* gate_b = (const float*)d_in[12];
    float* Z = (float*)d_out;

    k_swt    <<<BNUM * CIN, 256>>>(x);
    k_compose<<<dim3(9, 32), 256>>>(Wq, bq, Wk, bk, Wv, bv, in_w, in_b);
    k_qkv    <<<dim3(192, 3), 256>>>();
    k_attn   <<<dim3(16, HNUM, SNUM * BNUM * 2), 64>>>();
    k_merge  <<<384, 256>>>();
    k_meanred<<<dim3(SNUM, BNUM, 16), 128>>>();
    k_gate   <<<1, DMODEL>>>(out_w, out_b, gate_w, gate_b);
    k_final  <<<64, 256>>>(out_w, out_b, Z);
}

// round 6
// speedup vs baseline: 1.5820x; 1.5820x over previous
#include <cuda_runtime.h>

#define TFULL 2048
#define CIN   64
#define DMODEL 128
#define SNUM  3
#define BNUM  2
#define HNUM  8
#define DH    16

typedef unsigned int uint32;

__device__ __forceinline__ uint32 cvt_tf32(float x) {
    uint32 r; asm("cvt.rna.tf32.f32 %0,%1;" : "=r"(r) : "f"(x)); return r;
}
__device__ __forceinline__ void mma_tf32(float* d, const uint32* a, uint32 b0, uint32 b1) {
    asm volatile("mma.sync.aligned.m16n8k8.row.col.f32.tf32.tf32.f32 "
        "{%0,%1,%2,%3},{%4,%5,%6,%7},{%8,%9},{%0,%1,%2,%3};"
        : "+f"(d[0]), "+f"(d[1]), "+f"(d[2]), "+f"(d[3])
        : "r"(a[0]), "r"(a[1]), "r"(a[2]), "r"(a[3]), "r"(b0), "r"(b1));
}

// ---------------- wavelet filters ----------------
__constant__ float c_DEC_LO[8] = {
    -0.010597401784997278f,  0.032883011666982945f,  0.030841381835986965f,
    -0.18703481171888114f,  -0.02798376941698385f,   0.6308807679295904f,
     0.7148465705525415f,    0.23037781330885523f };
__constant__ float c_DEC_HI[8] = {
    -0.23037781330885523f,   0.7148465705525415f,   -0.6308807679295904f,
    -0.02798376941698385f,   0.18703481171888114f,   0.030841381835986965f,
    -0.032883011666982945f, -0.010597401784997278f };

// ---------------- scratch ----------------
__device__ float g_W   [SNUM*BNUM*TFULL*CIN];
__device__ float g_A   [SNUM*3*DMODEL*CIN];
__device__ float g_cb  [SNUM*3*DMODEL];
__device__ float g_q   [SNUM*BNUM*TFULL*DMODEL];
__device__ float g_k   [SNUM*BNUM*TFULL*DMODEL];
__device__ float g_v   [SNUM*BNUM*TFULL*DMODEL];
__device__ float g_o   [SNUM*BNUM*TFULL*DMODEL];
__device__ float g_meanp[SNUM*BNUM*16*DMODEL];
__device__ float g_gate[BNUM*SNUM];

// ================= K0: stationary wavelet transform =================
__global__ void k_swt(const float* __restrict__ x) {
    __shared__ float sh[2][TFULL];
    const int b = blockIdx.x >> 6;
    const int c = blockIdx.x & 63;
    const int tid = threadIdx.x;

    for (int t = tid; t < TFULL; t += 256)
        sh[0][t] = x[(b * TFULL + t) * CIN + c];
    __syncthreads();

    int cur = 0;
    for (int j = 0; j < 3; j++) {
        const int step = 1 << j;
        for (int t = tid; t < TFULL; t += 256) {
            float d = 0.f, a = 0.f;
#pragma unroll
            for (int l = 0; l < 8; l++) {
                float val = sh[cur][(t - l * step) & (TFULL - 1)];
                d += val * c_DEC_HI[l];
                a += val * c_DEC_LO[l];
            }
            g_W[(((2 - j) * BNUM + b) * TFULL + t) * CIN + c] = d;
            sh[cur ^ 1][t] = a;
        }
        __syncthreads();
        cur ^= 1;
    }
}

// ================= K1: compose (in_w x Wqkv) weights + biases =================
__global__ void k_compose(const float* __restrict__ Wq, const float* __restrict__ bq,
                          const float* __restrict__ Wk, const float* __restrict__ bk,
                          const float* __restrict__ Wv, const float* __restrict__ bv,
                          const float* __restrict__ in_w, const float* __restrict__ in_b) {
    const int sw = blockIdx.x;
    const int s = sw / 3, w = sw % 3;
    const float* Wx = (w == 0) ? Wq : (w == 1) ? Wk : Wv;
    const float* bx = (w == 0) ? bq : (w == 1) ? bk : bv;

    const int idx = blockIdx.y * 256 + threadIdx.x;
    const int e = idx >> 6, c = idx & 63;
    const float* iw = in_w + (w * DMODEL + e) * DMODEL;
    const float* wc = Wx + s * DMODEL * CIN + c;
    float acc = 0.f;
#pragma unroll 4
    for (int dd = 0; dd < DMODEL; dd++) acc += iw[dd] * wc[dd * CIN];
    g_A[(sw * DMODEL + e) * CIN + c] = acc;

    if (blockIdx.y == 0 && threadIdx.x < DMODEL) {
        const int ee = threadIdx.x;
        const float* iw2 = in_w + (w * DMODEL + ee) * DMODEL;
        float bb = in_b[w * DMODEL + ee];
#pragma unroll 4
        for (int dd = 0; dd < DMODEL; dd++) bb += iw2[dd] * bx[s * DMODEL + dd];
        g_cb[sw * DMODEL + ee] = bb;
    }
}

// ================= K2: fused q/k/v projection GEMM =================
__global__ void __launch_bounds__(256) k_qkv() {
    __shared__ float shW[64][33];
    __shared__ float shA[128][33];
    const int row0 = blockIdx.x * 64;
    const int w = blockIdx.y;
    const int s = row0 >> 12;
    const int tid = threadIdx.x;
    const int ty = tid >> 4, tx = tid & 15;
    const float* Abase = g_A + (s * 3 + w) * DMODEL * CIN;

    float acc[4][8];
#pragma unroll
    for (int i = 0; i < 4; i++)
#pragma unroll
        for (int j = 0; j < 8; j++) acc[i][j] = 0.f;

    for (int c0 = 0; c0 < CIN; c0 += 32) {
#pragma unroll
        for (int i = 0; i < 8; i++) {
            int lin = tid + i * 256;
            shW[lin >> 5][lin & 31] = g_W[(row0 + (lin >> 5)) * CIN + c0 + (lin & 31)];
        }
#pragma unroll
        for (int i = 0; i < 16; i++) {
            int lin = tid + i * 256;
            shA[lin >> 5][lin & 31] = Abase[(lin >> 5) * CIN + c0 + (lin & 31)];
        }
        __syncthreads();
#pragma unroll
        for (int cc = 0; cc < 32; cc++) {
            float wr[4], ar[8];
#pragma unroll
            for (int i = 0; i < 4; i++) wr[i] = shW[i * 16 + ty][cc];
#pragma unroll
            for (int j = 0; j < 8; j++) ar[j] = shA[j * 16 + tx][cc];
#pragma unroll
            for (int i = 0; i < 4; i++)
#pragma unroll
                for (int j = 0; j < 8; j++) acc[i][j] += wr[i] * ar[j];
        }
        __syncthreads();
    }

    float* out = (w == 0) ? g_q : (w == 1) ? g_k : g_v;
    const float* cb = g_cb + (s * 3 + w) * DMODEL;
#pragma unroll
    for (int i = 0; i < 4; i++) {
        int r = row0 + i * 16 + ty;
#pragma unroll
        for (int j = 0; j < 8; j++) {
            int e = j * 16 + tx;
            out[r * DMODEL + e] = acc[i][j] + cb[e];
        }
    }
}

// ================= K3: flash attention on tensor cores (tf32 mma) =================
// grid: (32 q-tiles of 64, 8 heads, 6 s*b). block 128 (4 warps, 16 q-rows/warp).
// QK^T in 3xTF32 (exact to ~1e-7), softmax in fragments, P*V in tf32.
// Key-column permutation sigma(p) = (p>>1)+(p&1)*4 makes the S C-fragment
// layout identical to the A-fragment layout needed for P*V (no shuffles).
#define KSTRIDE 20
#define VSTRIDE 24
__global__ void __launch_bounds__(128) k_attn() {
    __shared__ float sKhi[64 * KSTRIDE];
    __shared__ float sKlo[64 * KSTRIDE];
    __shared__ float sV  [64 * VSTRIDE];

    const int tid  = threadIdx.x;
    const int warp = tid >> 5, lane = tid & 31;
    const int gid  = lane >> 2, tig = lane & 3;
    const int qt = blockIdx.x, h = blockIdx.y, sb = blockIdx.z;
    const int qbase = qt * 64 + warp * 16;

    const float sc = 0.25f * 1.4426950408889634f;   // 1/sqrt(DH) * log2(e)

    // ---- load Q rows (gid, gid+8), split hi/lo tf32 ----
    const float* qr = g_q + ((size_t)(sb * TFULL) + qbase + gid) * DMODEL + h * DH;
    float qv[8];
    qv[0] = qr[tig];                 qv[1] = qr[tig + 4];
    qv[2] = qr[tig + 8];             qv[3] = qr[tig + 12];
    qv[4] = qr[8 * DMODEL + tig];    qv[5] = qr[8 * DMODEL + tig + 4];
    qv[6] = qr[8 * DMODEL + tig + 8];qv[7] = qr[8 * DMODEL + tig + 12];
    uint32 qhi[8], qlo[8];
#pragma unroll
    for (int i = 0; i < 8; i++) {
        float x = qv[i] * sc;
        qhi[i] = cvt_tf32(x);
        qlo[i] = cvt_tf32(x - __uint_as_float(qhi[i]));
    }
    // A fragments: kstep0 = cols [0,8), kstep1 = cols [8,16)
    uint32 ahi0[4] = { qhi[0], qhi[4], qhi[1], qhi[5] };
    uint32 alo0[4] = { qlo[0], qlo[4], qlo[1], qlo[5] };
    uint32 ahi1[4] = { qhi[2], qhi[6], qhi[3], qhi[7] };
    uint32 alo1[4] = { qlo[2], qlo[6], qlo[3], qlo[7] };

    float m_lo = -1e30f, m_hi = -1e30f, l_lo = 0.f, l_hi = 0.f;
    float oc[2][4];
#pragma unroll
    for (int nv = 0; nv < 2; nv++)
#pragma unroll
        for (int i = 0; i < 4; i++) oc[nv][i] = 0.f;

    const int sigma = (gid >> 1) + ((gid & 1) << 2);   // key-col permutation

    for (int kc = 0; kc < TFULL; kc += 64) {
        // ---- fill smem: K split hi/lo, V pre-converted to tf32 ----
#pragma unroll
        for (int i = 0; i < 2; i++) {
            int idx = tid + i * 128;           // 256 float4 = 64 rows x 4
            int r = idx >> 2, c4 = idx & 3;
            size_t gidx = ((size_t)(sb * TFULL) + kc + r) * DMODEL + h * DH + c4 * 4;
            float4 kk = *(const float4*)(g_k + gidx);
            float4 khi, klo;
            khi.x = __uint_as_float(cvt_tf32(kk.x)); klo.x = __uint_as_float(cvt_tf32(kk.x - khi.x));
            khi.y = __uint_as_float(cvt_tf32(kk.y)); klo.y = __uint_as_float(cvt_tf32(kk.y - khi.y));
            khi.z = __uint_as_float(cvt_tf32(kk.z)); klo.z = __uint_as_float(cvt_tf32(kk.z - khi.z));
            khi.w = __uint_as_float(cvt_tf32(kk.w)); klo.w = __uint_as_float(cvt_tf32(kk.w - khi.w));
            *(float4*)(sKhi + r * KSTRIDE + c4 * 4) = khi;
            *(float4*)(sKlo + r * KSTRIDE + c4 * 4) = klo;
            float4 vv = *(const float4*)(g_v + gidx);
            float4 vt;
            vt.x = __uint_as_float(cvt_tf32(vv.x));
            vt.y = __uint_as_float(cvt_tf32(vv.y));
            vt.z = __uint_as_float(cvt_tf32(vv.z));
            vt.w = __uint_as_float(cvt_tf32(vv.w));
            *(float4*)(sV + r * VSTRIDE + c4 * 4) = vt;
        }
        __syncthreads();

        // ---- S = Q K^T (3xTF32), C layout pre-permuted for PV ----
        float cS[8][4];
#pragma unroll
        for (int nt = 0; nt < 8; nt++) {
            cS[nt][0] = 0.f; cS[nt][1] = 0.f; cS[nt][2] = 0.f; cS[nt][3] = 0.f;
            const int key = 8 * nt + sigma;
            const float* kh = sKhi + key * KSTRIDE;
            const float* kl = sKlo + key * KSTRIDE;
            uint32 b0h = __float_as_uint(kh[tig]);
            uint32 b1h = __float_as_uint(kh[tig + 4]);
            uint32 b0l = __float_as_uint(kl[tig]);
            uint32 b1l = __float_as_uint(kl[tig + 4]);
            mma_tf32(cS[nt], ahi0, b0h, b1h);
            mma_tf32(cS[nt], alo0, b0h, b1h);
            mma_tf32(cS[nt], ahi0, b0l, b1l);
            b0h = __float_as_uint(kh[tig + 8]);
            b1h = __float_as_uint(kh[tig + 12]);
            b0l = __float_as_uint(kl[tig + 8]);
            b1l = __float_as_uint(kl[tig + 12]);
            mma_tf32(cS[nt], ahi1, b0h, b1h);
            mma_tf32(cS[nt], alo1, b0h, b1h);
            mma_tf32(cS[nt], ahi1, b0l, b1l);
        }

        // ---- online softmax on fragments ----
        float mx0 = m_lo, mx1 = m_hi;
#pragma unroll
        for (int nt = 0; nt < 8; nt++) {
            mx0 = fmaxf(mx0, fmaxf(cS[nt][0], cS[nt][1]));
            mx1 = fmaxf(mx1, fmaxf(cS[nt][2], cS[nt][3]));
        }
        mx0 = fmaxf(mx0, __shfl_xor_sync(0xffffffffu, mx0, 1));
        mx0 = fmaxf(mx0, __shfl_xor_sync(0xffffffffu, mx0, 2));
        mx1 = fmaxf(mx1, __shfl_xor_sync(0xffffffffu, mx1, 1));
        mx1 = fmaxf(mx1, __shfl_xor_sync(0xffffffffu, mx1, 2));
        float cr0 = exp2f(m_lo - mx0), cr1 = exp2f(m_hi - mx1);
        m_lo = mx0; m_hi = mx1;
        l_lo *= cr0; l_hi *= cr1;
#pragma unroll
        for (int nv = 0; nv < 2; nv++) {
            oc[nv][0] *= cr0; oc[nv][1] *= cr0;
            oc[nv][2] *= cr1; oc[nv][3] *= cr1;
        }
        uint32 pt[8][4];
#pragma unroll
        for (int nt = 0; nt < 8; nt++) {
            float p0 = exp2f(cS[nt][0] - m_lo);
            float p1 = exp2f(cS[nt][1] - m_lo);
            float p2 = exp2f(cS[nt][2] - m_hi);
            float p3 = exp2f(cS[nt][3] - m_hi);
            l_lo += p0 + p1;
            l_hi += p2 + p3;
            pt[nt][0] = cvt_tf32(p0);
            pt[nt][1] = cvt_tf32(p1);
            pt[nt][2] = cvt_tf32(p2);
            pt[nt][3] = cvt_tf32(p3);
        }

        // ---- O += P V  (A fragment = permuted C fragment, identity mapping) ----
#pragma unroll
        for (int j = 0; j < 8; j++) {
            uint32 ap[4] = { pt[j][0], pt[j][2], pt[j][1], pt[j][3] };
            const float* v0 = sV + (8 * j + tig) * VSTRIDE;
            const float* v1 = sV + (8 * j + tig + 4) * VSTRIDE;
            uint32 b0 = __float_as_uint(v0[gid]);
            uint32 b1 = __float_as_uint(v1[gid]);
            mma_tf32(oc[0], ap, b0, b1);
            b0 = __float_as_uint(v0[gid + 8]);
            b1 = __float_as_uint(v1[gid + 8]);
            mma_tf32(oc[1], ap, b0, b1);
        }
        __syncthreads();
    }

    // ---- finalize: sum l across quad, normalize, store ----
    l_lo += __shfl_xor_sync(0xffffffffu, l_lo, 1);
    l_lo += __shfl_xor_sync(0xffffffffu, l_lo, 2);
    l_hi += __shfl_xor_sync(0xffffffffu, l_hi, 1);
    l_hi += __shfl_xor_sync(0xffffffffu, l_hi, 2);
    float inv_lo = 1.f / l_lo;
    float inv_hi = 1.f / l_hi;

    float* ob = g_o + ((size_t)(sb * TFULL) + qbase + gid) * DMODEL + h * DH;
#pragma unroll
    for (int nv = 0; nv < 2; nv++) {
        *(float2*)(ob + 2 * tig + 8 * nv) =
            make_float2(oc[nv][0] * inv_lo, oc[nv][1] * inv_lo);
        *(float2*)(ob + 8 * DMODEL + 2 * tig + 8 * nv) =
            make_float2(oc[nv][2] * inv_hi, oc[nv][3] * inv_hi);
    }
}

// ================= K4: partial t-sums =================
__global__ void k_meanred() {
    const int s = blockIdx.x, b = blockIdx.y, ch = blockIdx.z;
    const int d = threadIdx.x;
    const float* base = g_o + (((size_t)(s * BNUM + b) * TFULL) + ch * 128) * DMODEL + d;
    float sum = 0.f;
#pragma unroll 8
    for (int t = 0; t < 128; t++) sum += base[t * DMODEL];
    g_meanp[((s * BNUM + b) * 16 + ch) * DMODEL + d] = sum;
}

// ================= K5: gate computation =================
__global__ void k_gate(const float* __restrict__ out_w, const float* __restrict__ out_b,
                       const float* __restrict__ gate_w, const float* __restrict__ gate_b) {
    __shared__ float sh_m[DMODEL];
    __shared__ float sh_gf[DMODEL];
    __shared__ float sh_lg[SNUM];
    const int d = threadIdx.x;
    for (int b = 0; b < BNUM; b++) {
        float mv = 0.f;
#pragma unroll
        for (int s = 0; s < SNUM; s++)
#pragma unroll
            for (int c = 0; c < 16; c++)
                mv += g_meanp[((s * BNUM + b) * 16 + c) * DMODEL + d];
        sh_m[d] = mv;
        __syncthreads();
        float acc = 0.f;
        const float* ow = out_w + d * DMODEL;
#pragma unroll 4
        for (int dd = 0; dd < DMODEL; dd++) acc += ow[dd] * sh_m[dd];
        sh_gf[d] = acc * (1.0f / (TFULL * SNUM)) + out_b[d];
        __syncthreads();
        if (d < SNUM) {
            float lg = gate_b[d];
            for (int dd = 0; dd < DMODEL; dd++) lg += sh_gf[dd] * gate_w[d * DMODEL + dd];
            sh_lg[d] = lg;
        }
        __syncthreads();
        if (d == 0) {
            float mx = fmaxf(sh_lg[0], fmaxf(sh_lg[1], sh_lg[2]));
            float e0 = __expf(sh_lg[0] - mx);
            float e1 = __expf(sh_lg[1] - mx);
            float e2 = __expf(sh_lg[2] - mx);
            float inv = 1.f / (e0 + e1 + e2);
            g_gate[b * 3 + 0] = e0 * inv;
            g_gate[b * 3 + 1] = e1 * inv;
            g_gate[b * 3 + 2] = e2 * inv;
        }
        __syncthreads();
    }
}

// ================= K6: gated combine + output projection =================
__global__ void __launch_bounds__(256) k_final(const float* __restrict__ out_w,
                                               const float* __restrict__ out_b,
                                               float* __restrict__ Z) {
    __shared__ float shI[64][33];
    __shared__ float shWt[128][33];
    const int row0 = blockIdx.x * 64;
    const int tid = threadIdx.x;
    const int b = row0 >> 11;
    const float gt0 = g_gate[b * 3 + 0];
    const float gt1 = g_gate[b * 3 + 1];
    const float gt2 = g_gate[b * 3 + 2];
    const int ty = tid >> 4, tx = tid & 15;
    const size_t SB = (size_t)BNUM * TFULL * DMODEL;

    float acc[4][8];
#pragma unroll
    for (int i = 0; i < 4; i++)
#pragma unroll
        for (int j = 0; j < 8; j++) acc[i][j] = 0.f;

    for (int c0 = 0; c0 < DMODEL; c0 += 32) {
#pragma unroll
        for (int i = 0; i < 8; i++) {
            int lin = tid + i * 256;
            int rr = lin >> 5, cc = lin & 31;
            size_t idx = (size_t)(row0 + rr) * DMODEL + c0 + cc;
            float v0 = g_o[idx];
            float v1 = g_o[SB + idx];
            float v2 = g_o[2 * SB + idx];
            shI[rr][cc] = gt0 * v0 + gt1 * v1 + gt2 * v2;
        }
#pragma unroll
        for (int i = 0; i < 16; i++) {
            int lin = tid + i * 256;
            shWt[lin >> 5][lin & 31] = out_w[(lin >> 5) * DMODEL + c0 + (lin & 31)];
        }
        __syncthreads();
#pragma unroll
        for (int cc = 0; cc < 32; cc++) {
            float ir[4], wr[8];
#pragma unroll
            for (int i = 0; i < 4; i++) ir[i] = shI[i * 16 + ty][cc];
#pragma unroll
            for (int j = 0; j < 8; j++) wr[j] = shWt[j * 16 + tx][cc];
#pragma unroll
            for (int i = 0; i < 4; i++)
#pragma unroll
                for (int j = 0; j < 8; j++) acc[i][j] += ir[i] * wr[j];
        }
        __syncthreads();
    }

#pragma unroll
    for (int i = 0; i < 4; i++) {
        int r = row0 + i * 16 + ty;
#pragma unroll
        for (int j = 0; j < 8; j++) {
            int e = j * 16 + tx;
            Z[(size_t)r * DMODEL + e] = acc[i][j] + out_b[e];
        }
    }
}

// ================= launch =================
extern "C" void kernel_launch(void* const* d_in, const int* in_sizes, int n_in,
                              void* d_out, int out_size) {
    const float* x      = (const float*)d_in[0];
    const float* Wq     = (const float*)d_in[1];
    const float* bq     = (const float*)d_in[2];
    const float* Wk     = (const float*)d_in[3];
    const float* bk     = (const float*)d_in[4];
    const float* Wv     = (const float*)d_in[5];
    const float* bv     = (const float*)d_in[6];
    const float* in_w   = (const float*)d_in[7];
    const float* in_b   = (const float*)d_in[8];
    const float* out_w  = (const float*)d_in[9];
    const float* out_b  = (const float*)d_in[10];
    const float* gate_w = (const float*)d_in[11];
    const float* gate_b = (const float*)d_in[12];
    float* Z = (float*)d_out;

    k_swt    <<<BNUM * CIN, 256>>>(x);
    k_compose<<<dim3(9, 32), 256>>>(Wq, bq, Wk, bk, Wv, bv, in_w, in_b);
    k_qkv    <<<dim3(192, 3), 256>>>();
    k_attn   <<<dim3(32, HNUM, SNUM * BNUM), 128>>>();
    k_meanred<<<dim3(SNUM, BNUM, 16), 128>>>();
    k_gate   <<<1, DMODEL>>>(out_w, out_b, gate_w, gate_b);
    k_final  <<<64, 256>>>(out_w, out_b, Z);
}